// round 3
// baseline (speedup 1.0000x reference)
#include <cuda_runtime.h>
#include <cstddef>

// Problem dims (fixed per reference)
#define B_    2
#define S_    2048
#define D_    2048
#define NH_   32
#define NKV_  8
#define HD_   64
#define M_    (B_ * S_)          // 4096
#define NQ_   (NH_ * HD_)        // 2048
#define NKVD_ (NKV_ * HD_)       // 512

// ---------------- scratch (no allocations allowed) ----------------
__device__ float g_q[(size_t)M_ * NQ_];     // raw q proj   (M, 2048)
__device__ float g_k[(size_t)M_ * NKVD_];   // raw k proj   (M, 512)
__device__ float g_v[(size_t)M_ * NKVD_];   // raw v proj   (M, 512)
__device__ float g_qn[(size_t)M_ * NQ_];    // normed+roped q, layout (B, NH, S, HD)
__device__ float g_kn[(size_t)M_ * NKVD_];  // normed+roped k, layout (B, NKV, S, HD)
__device__ float g_attn[(size_t)M_ * NQ_];  // attention out, layout (M, NH*HD)

// ---------------- SGEMM: C[M,N] = A[M,K] @ B[K,N], row-major, fp32 --------
// 128x128 tile, BK=8, 256 threads, 8x8 per thread.
#define BM 128
#define BN 128
#define BK 8
__global__ __launch_bounds__(256) void sgemm_kernel(
    const float* __restrict__ A, const float* __restrict__ B,
    float* __restrict__ C, int M, int N, int K)
{
    __shared__ float As[BK][BM];
    __shared__ float Bs[BK][BN];

    int t  = threadIdx.x;
    int tx = t & 15;          // 0..15
    int ty = t >> 4;          // 0..15
    int m0 = blockIdx.y * BM;
    int n0 = blockIdx.x * BN;

    float acc[8][8];
#pragma unroll
    for (int i = 0; i < 8; i++)
#pragma unroll
        for (int j = 0; j < 8; j++) acc[i][j] = 0.f;

    // A load: each thread one float4. arow 0..127, ak in {0,4}
    int arow = t >> 1;
    int ak   = (t & 1) * 4;
    // B load: each thread one float4. brow 0..7, bcol = (t%32)*4
    int brow = t >> 5;
    int bcol = (t & 31) * 4;

    const float* Aptr = A + (size_t)(m0 + arow) * K + ak;
    const float* Bptr = B + (size_t)brow * N + n0 + bcol;

    for (int k0 = 0; k0 < K; k0 += BK) {
        float4 a4 = *(const float4*)(Aptr + k0);
        As[ak + 0][arow] = a4.x;
        As[ak + 1][arow] = a4.y;
        As[ak + 2][arow] = a4.z;
        As[ak + 3][arow] = a4.w;
        *(float4*)&Bs[brow][bcol] = *(const float4*)(Bptr + (size_t)k0 * N);
        __syncthreads();

#pragma unroll
        for (int kk = 0; kk < BK; kk++) {
            float4 a0 = *(const float4*)&As[kk][ty * 8];
            float4 a1 = *(const float4*)&As[kk][ty * 8 + 4];
            float4 b0 = *(const float4*)&Bs[kk][tx * 8];
            float4 b1 = *(const float4*)&Bs[kk][tx * 8 + 4];
            float a[8] = {a0.x, a0.y, a0.z, a0.w, a1.x, a1.y, a1.z, a1.w};
            float b[8] = {b0.x, b0.y, b0.z, b0.w, b1.x, b1.y, b1.z, b1.w};
#pragma unroll
            for (int i = 0; i < 8; i++)
#pragma unroll
                for (int j = 0; j < 8; j++) acc[i][j] += a[i] * b[j];
        }
        __syncthreads();
    }

#pragma unroll
    for (int i = 0; i < 8; i++) {
        float4* cp = (float4*)(C + (size_t)(m0 + ty * 8 + i) * N + n0 + tx * 8);
        cp[0] = make_float4(acc[i][0], acc[i][1], acc[i][2], acc[i][3]);
        cp[1] = make_float4(acc[i][4], acc[i][5], acc[i][6], acc[i][7]);
    }
}

// ---------------- RMSNorm(HD=64) + RoPE, one warp per head-vector ----------
// in:  (M, nheads*64) row-major (proj output)
// out: (B, nheads, S, 64)
__global__ __launch_bounds__(256) void norm_rope_kernel(
    const float* __restrict__ in, float* __restrict__ out,
    const float* __restrict__ scale,
    const float* __restrict__ cosb, const float* __restrict__ sinb,
    int nheads)
{
    int warp = (blockIdx.x * blockDim.x + threadIdx.x) >> 5;
    int lane = threadIdx.x & 31;
    int row  = warp / nheads;          // b*S + s
    int h    = warp - row * nheads;
    int s    = row & (S_ - 1);
    int b    = row >> 11;              // row / S_

    const float* p = in + (size_t)row * (nheads * HD_) + h * HD_;
    float x0 = p[lane];
    float x1 = p[lane + 32];
    float ss = x0 * x0 + x1 * x1;
#pragma unroll
    for (int o = 16; o; o >>= 1) ss += __shfl_xor_sync(0xffffffffu, ss, o);
    float rr = rsqrtf(ss * (1.0f / HD_) + 1e-6f);
    float n0 = x0 * rr * scale[lane];
    float n1 = x1 * rr * scale[lane + 32];

    float c0 = cosb[s * HD_ + lane];
    float c1 = cosb[s * HD_ + lane + 32];
    float s0 = sinb[s * HD_ + lane];
    float s1 = sinb[s * HD_ + lane + 32];
    // rot = [-x2, x1]
    float o0 = n0 * c0 - n1 * s0;
    float o1 = n1 * c1 + n0 * s1;

    float* q = out + ((size_t)(b * nheads + h) * S_ + s) * HD_;
    q[lane]      = o0;
    q[lane + 32] = o1;
}

// ---------------- fp32 flash attention (causal, GQA) -----------------------
// grid: (S/64, B*NH), 256 threads. thread t: row r=t/4, group g=t%4.
// Each thread owns cols/dims {g+4i : i<16}. Smem stride 68 -> conflict-free.
#define BQ  64
#define BKT 64
#define LDS_ 68
#define ATTN_SMEM (4 * BQ * LDS_ * 4)  // 69632 bytes

__global__ __launch_bounds__(256) void flash_attn_kernel(
    const float* __restrict__ qn, const float* __restrict__ kn,
    const float* __restrict__ v, float* __restrict__ outa)
{
    extern __shared__ float sm[];
    float* Qs = sm;
    float* Ks = sm + BQ * LDS_;
    float* Vs = sm + 2 * BQ * LDS_;
    float* Ps = sm + 3 * BQ * LDS_;

    int t = threadIdx.x;
    int r = t >> 2;
    int g = t & 3;
    int bh = blockIdx.y;               // b*NH + h
    int b  = bh >> 5;                  // / NH_
    int h  = bh & 31;
    int hk = h >> 2;                   // GQA ratio 4
    int q0 = blockIdx.x * BQ;

    const float* qb = qn + ((size_t)bh * S_ + q0) * HD_;
#pragma unroll
    for (int u = 0; u < (BQ * HD_) / 256; u++) {
        int idx = u * 256 + t;
        Qs[(idx >> 6) * LDS_ + (idx & 63)] = qb[idx] * 0.125f;  // 1/sqrt(64)
    }

    float acc[16];
#pragma unroll
    for (int i = 0; i < 16; i++) acc[i] = 0.f;
    float mrow = -1e30f, lrow = 0.f;

    const float* kb = kn + ((size_t)(b * NKV_ + hk) * S_) * HD_;
    const float* vb = v + (size_t)(b * S_) * NKVD_ + hk * HD_;

    for (int j0 = 0; j0 <= q0; j0 += BKT) {
        __syncthreads();
#pragma unroll
        for (int u = 0; u < (BKT * HD_) / 256; u++) {
            int idx = u * 256 + t;
            int rr = idx >> 6, d = idx & 63;
            Ks[rr * LDS_ + d] = kb[(size_t)(j0 + rr) * HD_ + d];
            Vs[rr * LDS_ + d] = vb[(size_t)(j0 + rr) * NKVD_ + d];
        }
        __syncthreads();

        float sc[16];
#pragma unroll
        for (int i = 0; i < 16; i++) sc[i] = 0.f;
#pragma unroll 8
        for (int d = 0; d < HD_; d++) {
            float qv = Qs[r * LDS_ + d];
#pragma unroll
            for (int i = 0; i < 16; i++)
                sc[i] += qv * Ks[(g + 4 * i) * LDS_ + d];
        }
        if (j0 == q0) {  // diagonal tile: mask c > r
#pragma unroll
            for (int i = 0; i < 16; i++)
                if (g + 4 * i > r) sc[i] = -1e30f;
        }

        float mx = sc[0];
#pragma unroll
        for (int i = 1; i < 16; i++) mx = fmaxf(mx, sc[i]);
        mx = fmaxf(mx, __shfl_xor_sync(0xffffffffu, mx, 1));
        mx = fmaxf(mx, __shfl_xor_sync(0xffffffffu, mx, 2));
        float mnew  = fmaxf(mrow, mx);
        float alpha = __expf(mrow - mnew);

        float p[16];
        float ps = 0.f;
#pragma unroll
        for (int i = 0; i < 16; i++) { p[i] = __expf(sc[i] - mnew); ps += p[i]; }
        ps += __shfl_xor_sync(0xffffffffu, ps, 1);
        ps += __shfl_xor_sync(0xffffffffu, ps, 2);
        lrow = lrow * alpha + ps;
        mrow = mnew;

#pragma unroll
        for (int i = 0; i < 16; i++) {
            acc[i] *= alpha;
            Ps[r * LDS_ + g + 4 * i] = p[i];
        }
        __syncwarp();

#pragma unroll 4
        for (int c = 0; c < BKT; c++) {
            float pv = Ps[r * LDS_ + c];
#pragma unroll
            for (int i = 0; i < 16; i++)
                acc[i] += pv * Vs[c * LDS_ + g + 4 * i];
        }
    }

    float inv = 1.0f / lrow;
    float* ob = outa + (size_t)(b * S_ + q0 + r) * NQ_ + h * HD_ + g;
#pragma unroll
    for (int i = 0; i < 16; i++) ob[4 * i] = acc[i] * inv;
}

// ---------------- launch --------------------------------------------------
extern "C" void kernel_launch(void* const* d_in, const int* in_sizes, int n_in,
                              void* d_out, int out_size)
{
    const float* x       = (const float*)d_in[0];
    const float* wq      = (const float*)d_in[1];
    const float* wk      = (const float*)d_in[2];
    const float* wv      = (const float*)d_in[3];
    const float* wo      = (const float*)d_in[4];
    const float* q_scale = (const float*)d_in[5];
    const float* k_scale = (const float*)d_in[6];
    const float* cosb    = (const float*)d_in[7];
    const float* sinb    = (const float*)d_in[8];
    // d_in[9] = mask: causal, computed inline — unused.
    float* out = (float*)d_out;

    float *q, *k, *v, *qn, *kn, *attn;
    cudaGetSymbolAddress((void**)&q,    g_q);
    cudaGetSymbolAddress((void**)&k,    g_k);
    cudaGetSymbolAddress((void**)&v,    g_v);
    cudaGetSymbolAddress((void**)&qn,   g_qn);
    cudaGetSymbolAddress((void**)&kn,   g_kn);
    cudaGetSymbolAddress((void**)&attn, g_attn);

    // QKV projections
    sgemm_kernel<<<dim3(NQ_ / BN, M_ / BM), 256>>>(x, wq, q, M_, NQ_, D_);
    sgemm_kernel<<<dim3(NKVD_ / BN, M_ / BM), 256>>>(x, wk, k, M_, NKVD_, D_);
    sgemm_kernel<<<dim3(NKVD_ / BN, M_ / BM), 256>>>(x, wv, v, M_, NKVD_, D_);

    // RMSNorm + RoPE (q: 131072 warps, k: 32768 warps; 8 warps/block)
    norm_rope_kernel<<<(M_ * NH_) / 8, 256>>>(q, qn, q_scale, cosb, sinb, NH_);
    norm_rope_kernel<<<(M_ * NKV_) / 8, 256>>>(k, kn, k_scale, cosb, sinb, NKV_);

    // Flash attention
    cudaFuncSetAttribute(flash_attn_kernel,
                         cudaFuncAttributeMaxDynamicSharedMemorySize, ATTN_SMEM);
    flash_attn_kernel<<<dim3(S_ / BQ, B_ * NH_), 256, ATTN_SMEM>>>(qn, kn, v, attn);

    // Output projection
    sgemm_kernel<<<dim3(D_ / BN, M_ / BM), 256>>>(attn, wo, out, M_, D_, NQ_);
}

// round 5
// speedup vs baseline: 1.4999x; 1.4999x over previous
#include <cuda_runtime.h>
#include <cstddef>
#include <cstdint>

// Problem dims (fixed per reference)
#define B_    2
#define S_    2048
#define D_    2048
#define NH_   32
#define NKV_  8
#define HD_   64
#define M_    (B_ * S_)          // 4096
#define NQ_   (NH_ * HD_)        // 2048
#define NKVD_ (NKV_ * HD_)       // 512

// ---------------- scratch (no allocations allowed) ----------------
__device__ float g_q[(size_t)M_ * NQ_];     // raw q proj   (M, 2048)
__device__ float g_k[(size_t)M_ * NKVD_];   // raw k proj   (M, 512)
__device__ float g_v[(size_t)M_ * NKVD_];   // raw v proj   (M, 512)
__device__ float g_qn[(size_t)M_ * NQ_];    // normed+roped q, layout (B, NH, S, HD)
__device__ float g_kn[(size_t)M_ * NKVD_];  // normed+roped k, layout (B, NKV, S, HD)
__device__ float g_attn[(size_t)M_ * NQ_];  // attention out, layout (M, NH*HD)

// ---------------- TF32 tensor-core GEMM ------------------------------------
// C[M,N] = A[M,K] @ B[K,N], row-major fp32 in/out, tf32 mma.sync compute.
// Block: 128x128x32. 8 warps in 2(M) x 4(N). Warp tile 64x32 = 4x4 m16n8 mma.
// As stride 36 floats, Bs stride 136 floats -> conflict-free fragment gathers.
#define GBM 128
#define GBN 128
#define GBK 32
#define AS_STRIDE 36
#define BS_STRIDE 136

__device__ __forceinline__ uint32_t f2tf32(float f) {
    uint32_t r;
    asm("cvt.rna.tf32.f32 %0, %1;" : "=r"(r) : "f"(f));
    return r;
}

__global__ __launch_bounds__(256) void tf32_gemm_kernel(
    const float* __restrict__ A, const float* __restrict__ B,
    float* __restrict__ C, int M, int N, int K)
{
    __shared__ float As[GBM * AS_STRIDE];   // [m][k] padded
    __shared__ float Bs[GBK * BS_STRIDE];   // [k][n] padded

    int t    = threadIdx.x;
    int wid  = t >> 5;
    int lane = t & 31;
    int warp_m = wid >> 2;      // 0..1 -> 64 rows each
    int warp_n = wid & 3;       // 0..3 -> 32 cols each
    int m0 = blockIdx.y * GBM;
    int n0 = blockIdx.x * GBN;

    int qrow = lane >> 2;       // 0..7
    int qcol = lane & 3;        // 0..3

    float acc[4][4][4];
#pragma unroll
    for (int mt = 0; mt < 4; mt++)
#pragma unroll
        for (int nt = 0; nt < 4; nt++)
#pragma unroll
            for (int e = 0; e < 4; e++) acc[mt][nt][e] = 0.f;

    for (int k0 = 0; k0 < K; k0 += GBK) {
        // load A tile 128x32 (4 float4 per thread)
#pragma unroll
        for (int u = 0; u < 4; u++) {
            int lin = u * 1024 + t * 4;
            int r = lin >> 5, c = lin & 31;
            float4 v = *(const float4*)(A + (size_t)(m0 + r) * K + k0 + c);
            *(float4*)(As + r * AS_STRIDE + c) = v;
        }
        // load B tile 32x128 (4 float4 per thread)
#pragma unroll
        for (int u = 0; u < 4; u++) {
            int lin = u * 1024 + t * 4;
            int r = lin >> 7, c = lin & 127;
            float4 v = *(const float4*)(B + (size_t)(k0 + r) * N + n0 + c);
            *(float4*)(Bs + r * BS_STRIDE + c) = v;
        }
        __syncthreads();

#pragma unroll
        for (int kk = 0; kk < 4; kk++) {   // 4 x k8 steps
            // B fragments (shared across m-tiles)
            uint32_t bf[4][2];
            int brow = kk * 8 + qcol;                // k index
            int bcol = warp_n * 32 + qrow;           // n index
#pragma unroll
            for (int nt = 0; nt < 4; nt++) {
                bf[nt][0] = f2tf32(Bs[brow * BS_STRIDE + bcol + nt * 8]);
                bf[nt][1] = f2tf32(Bs[(brow + 4) * BS_STRIDE + bcol + nt * 8]);
            }
#pragma unroll
            for (int mt = 0; mt < 4; mt++) {
                int arow = warp_m * 64 + mt * 16 + qrow;
                int acol = kk * 8 + qcol;
                uint32_t a0 = f2tf32(As[arow * AS_STRIDE + acol]);
                uint32_t a1 = f2tf32(As[(arow + 8) * AS_STRIDE + acol]);
                uint32_t a2 = f2tf32(As[arow * AS_STRIDE + acol + 4]);
                uint32_t a3 = f2tf32(As[(arow + 8) * AS_STRIDE + acol + 4]);
#pragma unroll
                for (int nt = 0; nt < 4; nt++) {
                    asm volatile(
                        "mma.sync.aligned.m16n8k8.row.col.f32.tf32.tf32.f32 "
                        "{%0,%1,%2,%3}, {%4,%5,%6,%7}, {%8,%9}, {%0,%1,%2,%3};\n"
                        : "+f"(acc[mt][nt][0]), "+f"(acc[mt][nt][1]),
                          "+f"(acc[mt][nt][2]), "+f"(acc[mt][nt][3])
                        : "r"(a0), "r"(a1), "r"(a2), "r"(a3),
                          "r"(bf[nt][0]), "r"(bf[nt][1]));
                }
            }
        }
        __syncthreads();
    }

    // epilogue: c0,c1 at (row, 2*qcol), c2,c3 at (row+8, 2*qcol)
#pragma unroll
    for (int mt = 0; mt < 4; mt++) {
#pragma unroll
        for (int nt = 0; nt < 4; nt++) {
            int row = m0 + warp_m * 64 + mt * 16 + qrow;
            int col = n0 + warp_n * 32 + nt * 8 + 2 * qcol;
            *(float2*)(C + (size_t)row * N + col) =
                make_float2(acc[mt][nt][0], acc[mt][nt][1]);
            *(float2*)(C + (size_t)(row + 8) * N + col) =
                make_float2(acc[mt][nt][2], acc[mt][nt][3]);
        }
    }
}

// ---------------- RMSNorm(HD=64) + RoPE, one warp per head-vector ----------
__global__ __launch_bounds__(256) void norm_rope_kernel(
    const float* __restrict__ in, float* __restrict__ out,
    const float* __restrict__ scale,
    const float* __restrict__ cosb, const float* __restrict__ sinb,
    int nheads)
{
    int warp = (blockIdx.x * blockDim.x + threadIdx.x) >> 5;
    int lane = threadIdx.x & 31;
    int row  = warp / nheads;          // b*S + s
    int h    = warp - row * nheads;
    int s    = row & (S_ - 1);
    int b    = row >> 11;              // row / S_

    const float* p = in + (size_t)row * (nheads * HD_) + h * HD_;
    float x0 = p[lane];
    float x1 = p[lane + 32];
    float ss = x0 * x0 + x1 * x1;
#pragma unroll
    for (int o = 16; o; o >>= 1) ss += __shfl_xor_sync(0xffffffffu, ss, o);
    float rr = rsqrtf(ss * (1.0f / HD_) + 1e-6f);
    float n0 = x0 * rr * scale[lane];
    float n1 = x1 * rr * scale[lane + 32];

    float c0 = cosb[s * HD_ + lane];
    float c1 = cosb[s * HD_ + lane + 32];
    float s0 = sinb[s * HD_ + lane];
    float s1 = sinb[s * HD_ + lane + 32];
    // rot = [-x2, x1]
    float o0 = n0 * c0 - n1 * s0;
    float o1 = n1 * c1 + n0 * s1;

    float* q = out + ((size_t)(b * nheads + h) * S_ + s) * HD_;
    q[lane]      = o0;
    q[lane + 32] = o1;
}

// ---------------- fp32 flash attention (causal, GQA) -----------------------
#define BQ  64
#define BKT 64
#define LDS_ 68
#define ATTN_SMEM (4 * BQ * LDS_ * 4)  // 69632 bytes

__global__ __launch_bounds__(256) void flash_attn_kernel(
    const float* __restrict__ qn, const float* __restrict__ kn,
    const float* __restrict__ v, float* __restrict__ outa)
{
    extern __shared__ float sm[];
    float* Qs = sm;
    float* Ks = sm + BQ * LDS_;
    float* Vs = sm + 2 * BQ * LDS_;
    float* Ps = sm + 3 * BQ * LDS_;

    int t = threadIdx.x;
    int r = t >> 2;
    int g = t & 3;
    int bh = blockIdx.y;               // b*NH + h
    int b  = bh >> 5;                  // / NH_
    int h  = bh & 31;
    int hk = h >> 2;                   // GQA ratio 4
    int q0 = blockIdx.x * BQ;

    const float* qb = qn + ((size_t)bh * S_ + q0) * HD_;
#pragma unroll
    for (int u = 0; u < (BQ * HD_) / 256; u++) {
        int idx = u * 256 + t;
        Qs[(idx >> 6) * LDS_ + (idx & 63)] = qb[idx] * 0.125f;  // 1/sqrt(64)
    }

    float acc[16];
#pragma unroll
    for (int i = 0; i < 16; i++) acc[i] = 0.f;
    float mrow = -1e30f, lrow = 0.f;

    const float* kb = kn + ((size_t)(b * NKV_ + hk) * S_) * HD_;
    const float* vb = v + (size_t)(b * S_) * NKVD_ + hk * HD_;

    for (int j0 = 0; j0 <= q0; j0 += BKT) {
        __syncthreads();
#pragma unroll
        for (int u = 0; u < (BKT * HD_) / 256; u++) {
            int idx = u * 256 + t;
            int rr = idx >> 6, d = idx & 63;
            Ks[rr * LDS_ + d] = kb[(size_t)(j0 + rr) * HD_ + d];
            Vs[rr * LDS_ + d] = vb[(size_t)(j0 + rr) * NKVD_ + d];
        }
        __syncthreads();

        float sc[16];
#pragma unroll
        for (int i = 0; i < 16; i++) sc[i] = 0.f;
#pragma unroll 8
        for (int d = 0; d < HD_; d++) {
            float qv = Qs[r * LDS_ + d];
#pragma unroll
            for (int i = 0; i < 16; i++)
                sc[i] += qv * Ks[(g + 4 * i) * LDS_ + d];
        }
        if (j0 == q0) {  // diagonal tile: mask c > r
#pragma unroll
            for (int i = 0; i < 16; i++)
                if (g + 4 * i > r) sc[i] = -1e30f;
        }

        float mx = sc[0];
#pragma unroll
        for (int i = 1; i < 16; i++) mx = fmaxf(mx, sc[i]);
        mx = fmaxf(mx, __shfl_xor_sync(0xffffffffu, mx, 1));
        mx = fmaxf(mx, __shfl_xor_sync(0xffffffffu, mx, 2));
        float mnew  = fmaxf(mrow, mx);
        float alpha = __expf(mrow - mnew);

        float p[16];
        float ps = 0.f;
#pragma unroll
        for (int i = 0; i < 16; i++) { p[i] = __expf(sc[i] - mnew); ps += p[i]; }
        ps += __shfl_xor_sync(0xffffffffu, ps, 1);
        ps += __shfl_xor_sync(0xffffffffu, ps, 2);
        lrow = lrow * alpha + ps;
        mrow = mnew;

#pragma unroll
        for (int i = 0; i < 16; i++) {
            acc[i] *= alpha;
            Ps[r * LDS_ + g + 4 * i] = p[i];
        }
        __syncwarp();

#pragma unroll 4
        for (int c = 0; c < BKT; c++) {
            float pv = Ps[r * LDS_ + c];
#pragma unroll
            for (int i = 0; i < 16; i++)
                acc[i] += pv * Vs[c * LDS_ + g + 4 * i];
        }
    }

    float inv = 1.0f / lrow;
    float* ob = outa + (size_t)(b * S_ + q0 + r) * NQ_ + h * HD_ + g;
#pragma unroll
    for (int i = 0; i < 16; i++) ob[4 * i] = acc[i] * inv;
}

// ---------------- launch --------------------------------------------------
extern "C" void kernel_launch(void* const* d_in, const int* in_sizes, int n_in,
                              void* d_out, int out_size)
{
    const float* x       = (const float*)d_in[0];
    const float* wq      = (const float*)d_in[1];
    const float* wk      = (const float*)d_in[2];
    const float* wv      = (const float*)d_in[3];
    const float* wo      = (const float*)d_in[4];
    const float* q_scale = (const float*)d_in[5];
    const float* k_scale = (const float*)d_in[6];
    const float* cosb    = (const float*)d_in[7];
    const float* sinb    = (const float*)d_in[8];
    // d_in[9] = mask: causal, computed inline — unused.
    float* out = (float*)d_out;

    float *q, *k, *v, *qn, *kn, *attn;
    cudaGetSymbolAddress((void**)&q,    g_q);
    cudaGetSymbolAddress((void**)&k,    g_k);
    cudaGetSymbolAddress((void**)&v,    g_v);
    cudaGetSymbolAddress((void**)&qn,   g_qn);
    cudaGetSymbolAddress((void**)&kn,   g_kn);
    cudaGetSymbolAddress((void**)&attn, g_attn);

    // QKV projections (tf32 tensor cores)
    tf32_gemm_kernel<<<dim3(NQ_ / GBN, M_ / GBM), 256>>>(x, wq, q, M_, NQ_, D_);
    tf32_gemm_kernel<<<dim3(NKVD_ / GBN, M_ / GBM), 256>>>(x, wk, k, M_, NKVD_, D_);
    tf32_gemm_kernel<<<dim3(NKVD_ / GBN, M_ / GBM), 256>>>(x, wv, v, M_, NKVD_, D_);

    // RMSNorm + RoPE
    norm_rope_kernel<<<(M_ * NH_) / 8, 256>>>(q, qn, q_scale, cosb, sinb, NH_);
    norm_rope_kernel<<<(M_ * NKV_) / 8, 256>>>(k, kn, k_scale, cosb, sinb, NKV_);

    // Flash attention
    cudaFuncSetAttribute(flash_attn_kernel,
                         cudaFuncAttributeMaxDynamicSharedMemorySize, ATTN_SMEM);
    flash_attn_kernel<<<dim3(S_ / BQ, B_ * NH_), 256, ATTN_SMEM>>>(qn, kn, v, attn);

    // Output projection (tf32 tensor cores)
    tf32_gemm_kernel<<<dim3(D_ / GBN, M_ / GBM), 256>>>(attn, wo, out, M_, D_, NQ_);
}

// round 9
// speedup vs baseline: 1.6177x; 1.0785x over previous
#include <cuda_runtime.h>
#include <cstddef>
#include <cstdint>

// Problem dims (fixed per reference)
#define B_    2
#define S_    2048
#define D_    2048
#define NH_   32
#define NKV_  8
#define HD_   64
#define M_    (B_ * S_)          // 4096
#define NQ_   (NH_ * HD_)        // 2048
#define NKVD_ (NKV_ * HD_)       // 512

// ---------------- scratch (no allocations allowed) ----------------
__device__ float g_q[(size_t)M_ * NQ_];
__device__ float g_k[(size_t)M_ * NKVD_];
__device__ float g_v[(size_t)M_ * NKVD_];
__device__ float g_qn[(size_t)M_ * NQ_];    // (B, NH, S, HD)
__device__ float g_kn[(size_t)M_ * NKVD_];  // (B, NKV, S, HD)
__device__ float g_attn[(size_t)M_ * NQ_];  // (M, NH*HD)

// ---------------- TF32 tensor-core GEMM, 2-stage cp.async pipeline ---------
// C[M,N] = A[M,K] @ B[K,N], row-major fp32, tf32 mma.sync.
// Block 128x128x32, 8 warps (2M x 4N), warp tile 64x32 (4x4 m16n8k8).
#define GBM 128
#define GBN 128
#define GBK 32
#define AS_STRIDE 36
#define BS_STRIDE 136
#define A_SZ (GBM * AS_STRIDE)   // 4608 floats
#define B_SZ (GBK * BS_STRIDE)   // 4352 floats
#define STAGE_SZ (A_SZ + B_SZ)
#define GEMM_SMEM (2 * STAGE_SZ * 4)   // 71680 bytes

__device__ __forceinline__ uint32_t f2tf32(float f) {
    uint32_t r;
    asm("cvt.rna.tf32.f32 %0, %1;" : "=r"(r) : "f"(f));
    return r;
}

__device__ __forceinline__ void gemm_issue_tile(
    const float* __restrict__ A, const float* __restrict__ B,
    int N, int K, int m0, int n0, int k0,
    float* As, float* Bs, int t)
{
#pragma unroll
    for (int u = 0; u < 4; u++) {
        int lin = u * 1024 + t * 4;
        int r = lin >> 5, c = lin & 31;
        const float* gp = A + (size_t)(m0 + r) * K + k0 + c;
        uint32_t sp = (uint32_t)__cvta_generic_to_shared(As + r * AS_STRIDE + c);
        asm volatile("cp.async.cg.shared.global [%0], [%1], 16;\n" :: "r"(sp), "l"(gp));
    }
#pragma unroll
    for (int u = 0; u < 4; u++) {
        int lin = u * 1024 + t * 4;
        int r = lin >> 7, c = lin & 127;
        const float* gp = B + (size_t)(k0 + r) * N + n0 + c;
        uint32_t sp = (uint32_t)__cvta_generic_to_shared(Bs + r * BS_STRIDE + c);
        asm volatile("cp.async.cg.shared.global [%0], [%1], 16;\n" :: "r"(sp), "l"(gp));
    }
    asm volatile("cp.async.commit_group;\n");
}

__global__ __launch_bounds__(256) void tf32_gemm_kernel(
    const float* __restrict__ A, const float* __restrict__ B,
    float* __restrict__ C, int M, int N, int K)
{
    extern __shared__ float gsm[];

    int t    = threadIdx.x;
    int wid  = t >> 5;
    int lane = t & 31;
    int warp_m = wid >> 2;
    int warp_n = wid & 3;
    int m0 = blockIdx.y * GBM;
    int n0 = blockIdx.x * GBN;
    int qrow = lane >> 2;
    int qcol = lane & 3;

    float acc[4][4][4];
#pragma unroll
    for (int mt = 0; mt < 4; mt++)
#pragma unroll
        for (int nt = 0; nt < 4; nt++)
#pragma unroll
            for (int e = 0; e < 4; e++) acc[mt][nt][e] = 0.f;

    int ntiles = K / GBK;
    // prologue
    gemm_issue_tile(A, B, N, K, m0, n0, 0, gsm, gsm + A_SZ, t);

    for (int it = 0; it < ntiles; it++) {
        int cur = it & 1;
        int nxt = cur ^ 1;
        bool has_next = (it + 1) < ntiles;
        if (has_next)
            gemm_issue_tile(A, B, N, K, m0, n0, (it + 1) * GBK,
                            gsm + nxt * STAGE_SZ, gsm + nxt * STAGE_SZ + A_SZ, t);
        if (has_next) asm volatile("cp.async.wait_group 1;\n");
        else          asm volatile("cp.async.wait_group 0;\n");
        __syncthreads();

        const float* As = gsm + cur * STAGE_SZ;
        const float* Bs = As + A_SZ;

#pragma unroll
        for (int kk = 0; kk < 4; kk++) {
            uint32_t bf[4][2];
            int brow = kk * 8 + qcol;
            int bcol = warp_n * 32 + qrow;
#pragma unroll
            for (int nt = 0; nt < 4; nt++) {
                bf[nt][0] = f2tf32(Bs[brow * BS_STRIDE + bcol + nt * 8]);
                bf[nt][1] = f2tf32(Bs[(brow + 4) * BS_STRIDE + bcol + nt * 8]);
            }
#pragma unroll
            for (int mt = 0; mt < 4; mt++) {
                int arow = warp_m * 64 + mt * 16 + qrow;
                int acol = kk * 8 + qcol;
                uint32_t a0 = f2tf32(As[arow * AS_STRIDE + acol]);
                uint32_t a1 = f2tf32(As[(arow + 8) * AS_STRIDE + acol]);
                uint32_t a2 = f2tf32(As[arow * AS_STRIDE + acol + 4]);
                uint32_t a3 = f2tf32(As[(arow + 8) * AS_STRIDE + acol + 4]);
#pragma unroll
                for (int nt = 0; nt < 4; nt++) {
                    asm volatile(
                        "mma.sync.aligned.m16n8k8.row.col.f32.tf32.tf32.f32 "
                        "{%0,%1,%2,%3}, {%4,%5,%6,%7}, {%8,%9}, {%0,%1,%2,%3};\n"
                        : "+f"(acc[mt][nt][0]), "+f"(acc[mt][nt][1]),
                          "+f"(acc[mt][nt][2]), "+f"(acc[mt][nt][3])
                        : "r"(a0), "r"(a1), "r"(a2), "r"(a3),
                          "r"(bf[nt][0]), "r"(bf[nt][1]));
                }
            }
        }
        __syncthreads();   // protect 'cur' buffer before it is re-issued next iter
    }

#pragma unroll
    for (int mt = 0; mt < 4; mt++) {
#pragma unroll
        for (int nt = 0; nt < 4; nt++) {
            int row = m0 + warp_m * 64 + mt * 16 + qrow;
            int col = n0 + warp_n * 32 + nt * 8 + 2 * qcol;
            *(float2*)(C + (size_t)row * N + col) =
                make_float2(acc[mt][nt][0], acc[mt][nt][1]);
            *(float2*)(C + (size_t)(row + 8) * N + col) =
                make_float2(acc[mt][nt][2], acc[mt][nt][3]);
        }
    }
}

// ---------------- RMSNorm(HD=64) + RoPE, one warp per head-vector ----------
__global__ __launch_bounds__(256) void norm_rope_kernel(
    const float* __restrict__ in, float* __restrict__ out,
    const float* __restrict__ scale,
    const float* __restrict__ cosb, const float* __restrict__ sinb,
    int nheads)
{
    int warp = (blockIdx.x * blockDim.x + threadIdx.x) >> 5;
    int lane = threadIdx.x & 31;
    int row  = warp / nheads;
    int h    = warp - row * nheads;
    int s    = row & (S_ - 1);
    int b    = row >> 11;

    const float* p = in + (size_t)row * (nheads * HD_) + h * HD_;
    float x0 = p[lane];
    float x1 = p[lane + 32];
    float ss = x0 * x0 + x1 * x1;
#pragma unroll
    for (int o = 16; o; o >>= 1) ss += __shfl_xor_sync(0xffffffffu, ss, o);
    float rr = rsqrtf(ss * (1.0f / HD_) + 1e-6f);
    float n0 = x0 * rr * scale[lane];
    float n1 = x1 * rr * scale[lane + 32];

    float c0 = cosb[s * HD_ + lane];
    float c1 = cosb[s * HD_ + lane + 32];
    float s0 = sinb[s * HD_ + lane];
    float s1 = sinb[s * HD_ + lane + 32];
    float o0 = n0 * c0 - n1 * s0;
    float o1 = n1 * c1 + n0 * s1;

    float* q = out + ((size_t)(b * nheads + h) * S_ + s) * HD_;
    q[lane]      = o0;
    q[lane + 32] = o1;
}

// ---------------- fp32 flash attention (causal, GQA), vectorized ----------
// grid (S/64, B*NH), 256 thr. thread t: r=t/4, g=t%4.
// Score cols owned: c = g+4i (i<16)  -> QK float4 along d, conflict-free.
// Acc dims owned:   d = 16g+i (i<16) -> PV float4 via bit-swapped V chunks:
//   V value (row,d) stored at chunk T(d>>2), T(q)=((q&3)<<2)|(q>>2)
//   PV load addr = c*68 + 16j + 4g  (j=i>>2) -> 4 consecutive chunks/quad.
#define BQ  64
#define BKT 64
#define LDS_ 68
#define ATTN_SMEM (4 * BQ * LDS_ * 4)  // 69632 bytes

__global__ __launch_bounds__(256) void flash_attn_kernel(
    const float* __restrict__ qn, const float* __restrict__ kn,
    const float* __restrict__ v, float* __restrict__ outa)
{
    extern __shared__ float sm[];
    float* Qs = sm;
    float* Ks = sm + BQ * LDS_;
    float* Vs = sm + 2 * BQ * LDS_;
    float* Ps = sm + 3 * BQ * LDS_;

    int t = threadIdx.x;
    int r = t >> 2;
    int g = t & 3;
    int bh = blockIdx.y;
    int b  = bh >> 5;
    int h  = bh & 31;
    int hk = h >> 2;
    int q0 = blockIdx.x * BQ;

    const float* qb = qn + ((size_t)bh * S_ + q0) * HD_;
#pragma unroll
    for (int u = 0; u < 4; u++) {
        int idx4 = u * 256 + t;              // float4 index in 64x64 tile
        int row = idx4 >> 4, ch = idx4 & 15;
        float4 qv = *(const float4*)(qb + (size_t)row * HD_ + ch * 4);
        qv.x *= 0.125f; qv.y *= 0.125f; qv.z *= 0.125f; qv.w *= 0.125f;
        *(float4*)&Qs[row * LDS_ + ch * 4] = qv;
    }

    float acc[16];
#pragma unroll
    for (int i = 0; i < 16; i++) acc[i] = 0.f;
    float mrow = -1e30f, lrow = 0.f;

    const float* kb = kn + ((size_t)(b * NKV_ + hk) * S_) * HD_;
    const float* vb = v + (size_t)(b * S_) * NKVD_ + hk * HD_;

    for (int j0 = 0; j0 <= q0; j0 += BKT) {
        __syncthreads();
#pragma unroll
        for (int u = 0; u < 4; u++) {
            int idx4 = u * 256 + t;
            int row = idx4 >> 4, ch = idx4 & 15;
            *(float4*)&Ks[row * LDS_ + ch * 4] =
                *(const float4*)(kb + (size_t)(j0 + row) * HD_ + ch * 4);
            int tc = ((ch & 3) << 2) | (ch >> 2);   // bit-swap chunk
            *(float4*)&Vs[row * LDS_ + tc * 4] =
                *(const float4*)(vb + (size_t)(j0 + row) * NKVD_ + ch * 4);
        }
        __syncthreads();

        float sc[16];
#pragma unroll
        for (int i = 0; i < 16; i++) sc[i] = 0.f;
#pragma unroll 4
        for (int d0 = 0; d0 < HD_; d0 += 4) {
            float4 q4 = *(const float4*)&Qs[r * LDS_ + d0];
#pragma unroll
            for (int i = 0; i < 16; i++) {
                float4 k4 = *(const float4*)&Ks[(g + 4 * i) * LDS_ + d0];
                sc[i] += q4.x * k4.x + q4.y * k4.y + q4.z * k4.z + q4.w * k4.w;
            }
        }
        if (j0 == q0) {
#pragma unroll
            for (int i = 0; i < 16; i++)
                if (g + 4 * i > r) sc[i] = -1e30f;
        }

        float mx = sc[0];
#pragma unroll
        for (int i = 1; i < 16; i++) mx = fmaxf(mx, sc[i]);
        mx = fmaxf(mx, __shfl_xor_sync(0xffffffffu, mx, 1));
        mx = fmaxf(mx, __shfl_xor_sync(0xffffffffu, mx, 2));
        float mnew  = fmaxf(mrow, mx);
        float alpha = __expf(mrow - mnew);

        float p[16];
        float ps = 0.f;
#pragma unroll
        for (int i = 0; i < 16; i++) { p[i] = __expf(sc[i] - mnew); ps += p[i]; }
        ps += __shfl_xor_sync(0xffffffffu, ps, 1);
        ps += __shfl_xor_sync(0xffffffffu, ps, 2);
        lrow = lrow * alpha + ps;
        mrow = mnew;

#pragma unroll
        for (int i = 0; i < 16; i++) {
            acc[i] *= alpha;
            Ps[r * LDS_ + g + 4 * i] = p[i];
        }
        __syncwarp();

#pragma unroll 4
        for (int c = 0; c < BKT; c++) {
            float pv = Ps[r * LDS_ + c];
#pragma unroll
            for (int j = 0; j < 4; j++) {
                float4 v4 = *(const float4*)&Vs[c * LDS_ + 16 * j + 4 * g];
                acc[4 * j + 0] += pv * v4.x;
                acc[4 * j + 1] += pv * v4.y;
                acc[4 * j + 2] += pv * v4.z;
                acc[4 * j + 3] += pv * v4.w;
            }
        }
    }

    float inv = 1.0f / lrow;
    float* ob = outa + (size_t)(b * S_ + q0 + r) * NQ_ + h * HD_ + 16 * g;
#pragma unroll
    for (int j = 0; j < 4; j++) {
        float4 o4 = make_float4(acc[4 * j + 0] * inv, acc[4 * j + 1] * inv,
                                acc[4 * j + 2] * inv, acc[4 * j + 3] * inv);
        *(float4*)(ob + 4 * j) = o4;
    }
}

// ---------------- launch --------------------------------------------------
extern "C" void kernel_launch(void* const* d_in, const int* in_sizes, int n_in,
                              void* d_out, int out_size)
{
    const float* x       = (const float*)d_in[0];
    const float* wq      = (const float*)d_in[1];
    const float* wk      = (const float*)d_in[2];
    const float* wv      = (const float*)d_in[3];
    const float* wo      = (const float*)d_in[4];
    const float* q_scale = (const float*)d_in[5];
    const float* k_scale = (const float*)d_in[6];
    const float* cosb    = (const float*)d_in[7];
    const float* sinb    = (const float*)d_in[8];
    float* out = (float*)d_out;

    float *q, *k, *v, *qn, *kn, *attn;
    cudaGetSymbolAddress((void**)&q,    g_q);
    cudaGetSymbolAddress((void**)&k,    g_k);
    cudaGetSymbolAddress((void**)&v,    g_v);
    cudaGetSymbolAddress((void**)&qn,   g_qn);
    cudaGetSymbolAddress((void**)&kn,   g_kn);
    cudaGetSymbolAddress((void**)&attn, g_attn);

    cudaFuncSetAttribute(tf32_gemm_kernel,
                         cudaFuncAttributeMaxDynamicSharedMemorySize, GEMM_SMEM);
    cudaFuncSetAttribute(flash_attn_kernel,
                         cudaFuncAttributeMaxDynamicSharedMemorySize, ATTN_SMEM);

    // QKV projections (tf32 tensor cores, pipelined)
    tf32_gemm_kernel<<<dim3(NQ_ / GBN, M_ / GBM), 256, GEMM_SMEM>>>(x, wq, q, M_, NQ_, D_);
    tf32_gemm_kernel<<<dim3(NKVD_ / GBN, M_ / GBM), 256, GEMM_SMEM>>>(x, wk, k, M_, NKVD_, D_);
    tf32_gemm_kernel<<<dim3(NKVD_ / GBN, M_ / GBM), 256, GEMM_SMEM>>>(x, wv, v, M_, NKVD_, D_);

    // RMSNorm + RoPE
    norm_rope_kernel<<<(M_ * NH_) / 8, 256>>>(q, qn, q_scale, cosb, sinb, NH_);
    norm_rope_kernel<<<(M_ * NKV_) / 8, 256>>>(k, kn, k_scale, cosb, sinb, NKV_);

    // Flash attention (fp32)
    flash_attn_kernel<<<dim3(S_ / BQ, B_ * NH_), 256, ATTN_SMEM>>>(qn, kn, v, attn);

    // Output projection
    tf32_gemm_kernel<<<dim3(D_ / GBN, M_ / GBM), 256, GEMM_SMEM>>>(attn, wo, out, M_, D_, NQ_);
}

// round 12
// speedup vs baseline: 4.9087x; 3.0344x over previous
#include <cuda_runtime.h>
#include <cstddef>
#include <cstdint>

// Problem dims (fixed per reference)
#define B_    2
#define S_    2048
#define D_    2048
#define NH_   32
#define NKV_  8
#define HD_   64
#define M_    (B_ * S_)          // 4096
#define NQ_   (NH_ * HD_)        // 2048
#define NKVD_ (NKV_ * HD_)       // 512

// ---------------- scratch (no allocations allowed) ----------------
__device__ float g_q[(size_t)M_ * NQ_];
__device__ float g_k[(size_t)M_ * NKVD_];
__device__ float g_v[(size_t)M_ * NKVD_];
__device__ float g_qn[(size_t)M_ * NQ_];    // (B, NH, S, HD)  tf32-rounded, pre-scaled 1/8
__device__ float g_kn[(size_t)M_ * NKVD_];  // (B, NKV, S, HD) tf32-rounded
__device__ float g_attn[(size_t)M_ * NQ_];  // (M, NH*HD)      tf32-rounded at epilogue
__device__ float g_xr[(size_t)M_ * D_];     // tf32-rounded x
__device__ float g_wqr[(size_t)D_ * NQ_];
__device__ float g_wkr[(size_t)D_ * NKVD_];
__device__ float g_wvr[(size_t)D_ * NKVD_];
__device__ float g_wor[(size_t)NQ_ * D_];

__device__ __forceinline__ uint32_t f2tf32(float f) {
    uint32_t r;
    asm("cvt.rna.tf32.f32 %0, %1;" : "=r"(r) : "f"(f));
    return r;
}
__device__ __forceinline__ float rtf(float f) { return __uint_as_float(f2tf32(f)); }

__device__ __forceinline__ void mma_tf32(
    float& c0, float& c1, float& c2, float& c3,
    uint32_t a0, uint32_t a1, uint32_t a2, uint32_t a3,
    uint32_t b0, uint32_t b1)
{
    asm volatile(
        "mma.sync.aligned.m16n8k8.row.col.f32.tf32.tf32.f32 "
        "{%0,%1,%2,%3}, {%4,%5,%6,%7}, {%8,%9}, {%0,%1,%2,%3};\n"
        : "+f"(c0), "+f"(c1), "+f"(c2), "+f"(c3)
        : "r"(a0), "r"(a1), "r"(a2), "r"(a3), "r"(b0), "r"(b1));
}

// ---------------- elementwise tf32 pre-round -------------------------------
__global__ void round_tf32_kernel(const float4* __restrict__ in,
                                  float4* __restrict__ out, int n4)
{
    for (int i = blockIdx.x * blockDim.x + threadIdx.x; i < n4;
         i += gridDim.x * blockDim.x) {
        float4 v = in[i];
        v.x = rtf(v.x); v.y = rtf(v.y); v.z = rtf(v.z); v.w = rtf(v.w);
        out[i] = v;
    }
}

// ---------------- TF32 GEMM, 2-stage cp.async, NO inner-loop CVT -----------
#define GBM 128
#define GBN 128
#define GBK 32
#define AS_STRIDE 36
#define BS_STRIDE 136
#define A_SZ (GBM * AS_STRIDE)
#define B_SZ (GBK * BS_STRIDE)
#define STAGE_SZ (A_SZ + B_SZ)
#define GEMM_SMEM (2 * STAGE_SZ * 4)

__device__ __forceinline__ void gemm_issue_tile(
    const float* __restrict__ A, const float* __restrict__ B,
    int N, int K, int m0, int n0, int k0,
    float* As, float* Bs, int t)
{
#pragma unroll
    for (int u = 0; u < 4; u++) {
        int lin = u * 1024 + t * 4;
        int r = lin >> 5, c = lin & 31;
        const float* gp = A + (size_t)(m0 + r) * K + k0 + c;
        uint32_t sp = (uint32_t)__cvta_generic_to_shared(As + r * AS_STRIDE + c);
        asm volatile("cp.async.cg.shared.global [%0], [%1], 16;\n" :: "r"(sp), "l"(gp));
    }
#pragma unroll
    for (int u = 0; u < 4; u++) {
        int lin = u * 1024 + t * 4;
        int r = lin >> 7, c = lin & 127;
        const float* gp = B + (size_t)(k0 + r) * N + n0 + c;
        uint32_t sp = (uint32_t)__cvta_generic_to_shared(Bs + r * BS_STRIDE + c);
        asm volatile("cp.async.cg.shared.global [%0], [%1], 16;\n" :: "r"(sp), "l"(gp));
    }
    asm volatile("cp.async.commit_group;\n");
}

__global__ __launch_bounds__(256) void tf32_gemm_kernel(
    const float* __restrict__ A, const float* __restrict__ B,
    float* __restrict__ C, int M, int N, int K)
{
    extern __shared__ float gsm[];

    int t    = threadIdx.x;
    int wid  = t >> 5;
    int lane = t & 31;
    int warp_m = wid >> 2;
    int warp_n = wid & 3;
    int m0 = blockIdx.y * GBM;
    int n0 = blockIdx.x * GBN;
    int qrow = lane >> 2;
    int qcol = lane & 3;

    float acc[4][4][4];
#pragma unroll
    for (int mt = 0; mt < 4; mt++)
#pragma unroll
        for (int nt = 0; nt < 4; nt++)
#pragma unroll
            for (int e = 0; e < 4; e++) acc[mt][nt][e] = 0.f;

    int ntiles = K / GBK;
    gemm_issue_tile(A, B, N, K, m0, n0, 0, gsm, gsm + A_SZ, t);

    for (int it = 0; it < ntiles; it++) {
        int cur = it & 1;
        int nxt = cur ^ 1;
        bool has_next = (it + 1) < ntiles;
        if (has_next)
            gemm_issue_tile(A, B, N, K, m0, n0, (it + 1) * GBK,
                            gsm + nxt * STAGE_SZ, gsm + nxt * STAGE_SZ + A_SZ, t);
        if (has_next) asm volatile("cp.async.wait_group 1;\n");
        else          asm volatile("cp.async.wait_group 0;\n");
        __syncthreads();

        const uint32_t* As = (const uint32_t*)(gsm + cur * STAGE_SZ);
        const uint32_t* Bs = As + A_SZ;

#pragma unroll
        for (int kk = 0; kk < 4; kk++) {
            uint32_t bf[4][2];
            int brow = kk * 8 + qcol;
            int bcol = warp_n * 32 + qrow;
#pragma unroll
            for (int nt = 0; nt < 4; nt++) {
                bf[nt][0] = Bs[brow * BS_STRIDE + bcol + nt * 8];
                bf[nt][1] = Bs[(brow + 4) * BS_STRIDE + bcol + nt * 8];
            }
#pragma unroll
            for (int mt = 0; mt < 4; mt++) {
                int arow = warp_m * 64 + mt * 16 + qrow;
                int acol = kk * 8 + qcol;
                uint32_t a0 = As[arow * AS_STRIDE + acol];
                uint32_t a1 = As[(arow + 8) * AS_STRIDE + acol];
                uint32_t a2 = As[arow * AS_STRIDE + acol + 4];
                uint32_t a3 = As[(arow + 8) * AS_STRIDE + acol + 4];
#pragma unroll
                for (int nt = 0; nt < 4; nt++)
                    mma_tf32(acc[mt][nt][0], acc[mt][nt][1],
                             acc[mt][nt][2], acc[mt][nt][3],
                             a0, a1, a2, a3, bf[nt][0], bf[nt][1]);
            }
        }
        __syncthreads();
    }

#pragma unroll
    for (int mt = 0; mt < 4; mt++) {
#pragma unroll
        for (int nt = 0; nt < 4; nt++) {
            int row = m0 + warp_m * 64 + mt * 16 + qrow;
            int col = n0 + warp_n * 32 + nt * 8 + 2 * qcol;
            *(float2*)(C + (size_t)row * N + col) =
                make_float2(acc[mt][nt][0], acc[mt][nt][1]);
            *(float2*)(C + (size_t)(row + 8) * N + col) =
                make_float2(acc[mt][nt][2], acc[mt][nt][3]);
        }
    }
}

// ---------------- RMSNorm + RoPE, tf32-rounded output, optional scale ------
__global__ __launch_bounds__(256) void norm_rope_kernel(
    const float* __restrict__ in, float* __restrict__ out,
    const float* __restrict__ scale,
    const float* __restrict__ cosb, const float* __restrict__ sinb,
    int nheads, float smul)
{
    int warp = (blockIdx.x * blockDim.x + threadIdx.x) >> 5;
    int lane = threadIdx.x & 31;
    int row  = warp / nheads;
    int h    = warp - row * nheads;
    int s    = row & (S_ - 1);
    int b    = row >> 11;

    const float* p = in + (size_t)row * (nheads * HD_) + h * HD_;
    float x0 = p[lane];
    float x1 = p[lane + 32];
    float ss = x0 * x0 + x1 * x1;
#pragma unroll
    for (int o = 16; o; o >>= 1) ss += __shfl_xor_sync(0xffffffffu, ss, o);
    float rr = rsqrtf(ss * (1.0f / HD_) + 1e-6f);
    float n0 = x0 * rr * scale[lane];
    float n1 = x1 * rr * scale[lane + 32];

    float c0 = cosb[s * HD_ + lane];
    float c1 = cosb[s * HD_ + lane + 32];
    float s0 = sinb[s * HD_ + lane];
    float s1 = sinb[s * HD_ + lane + 32];
    float o0 = (n0 * c0 - n1 * s0) * smul;
    float o1 = (n1 * c1 + n0 * s1) * smul;

    float* q = out + ((size_t)(b * nheads + h) * S_ + s) * HD_;
    q[lane]      = rtf(o0);
    q[lane + 32] = rtf(o1);
}

// ---------------- tensor-core flash attention (causal, GQA) ----------------
// 128 threads (4 warps). CTA: 64 q-rows; warp w: rows 16w..16w+15.
// QK and PV via mma.m16n8k8.tf32. K/V tiles double-buffered cp.async.
#define AT_STRIDE 68
#define AT_TILE (64 * AT_STRIDE)
#define ATTN_SMEM_TC (5 * AT_TILE * 4)   // Q + 2*(K,V) = 87040 B

__global__ __launch_bounds__(128) void flash_attn_tc_kernel(
    const float* __restrict__ qn, const float* __restrict__ kn,
    const float* __restrict__ v, float* __restrict__ outa)
{
    extern __shared__ float sm[];
    float* Qs = sm;
    float* KV = sm + AT_TILE;    // [stage][K tile | V tile]

    int t = threadIdx.x;
    int lane = t & 31;
    int w = t >> 5;
    int qrow = lane >> 2;
    int qcol = lane & 3;
    int bh = blockIdx.y;
    int b  = bh >> 5;
    int h  = bh & 31;
    int hk = h >> 2;
    int q0 = blockIdx.x * 64;

    const float* kb = kn + ((size_t)(b * NKV_ + hk) * S_) * HD_;
    const float* vb = v + (size_t)(b * S_) * NKVD_ + hk * HD_;

    // load Q tile (values pre-scaled by 1/8 and tf32-rounded upstream)
    const float* qb = qn + ((size_t)bh * S_ + q0) * HD_;
#pragma unroll
    for (int u = 0; u < 8; u++) {
        int idx4 = u * 128 + t;
        int row = idx4 >> 4, ch = idx4 & 15;
        *(float4*)&Qs[row * AT_STRIDE + ch * 4] =
            *(const float4*)(qb + (size_t)row * HD_ + ch * 4);
    }

    // issue K/V tile j0 into stage s
    auto issue_kv = [&](int j0, int s) {
        float* Kd = KV + s * 2 * AT_TILE;
        float* Vd = Kd + AT_TILE;
#pragma unroll
        for (int u = 0; u < 8; u++) {
            int idx4 = u * 128 + t;
            int row = idx4 >> 4, ch = idx4 & 15;
            const float* gk = kb + (size_t)(j0 + row) * HD_ + ch * 4;
            uint32_t sk = (uint32_t)__cvta_generic_to_shared(Kd + row * AT_STRIDE + ch * 4);
            asm volatile("cp.async.cg.shared.global [%0], [%1], 16;\n" :: "r"(sk), "l"(gk));
            const float* gv = vb + (size_t)(j0 + row) * NKVD_ + ch * 4;
            uint32_t sv = (uint32_t)__cvta_generic_to_shared(Vd + row * AT_STRIDE + ch * 4);
            asm volatile("cp.async.cg.shared.global [%0], [%1], 16;\n" :: "r"(sv), "l"(gv));
        }
        asm volatile("cp.async.commit_group;\n");
    };

    issue_kv(0, 0);
    __syncthreads();   // Qs ready for fragment builds

    // Q fragments: [ks][a0..a3]
    uint32_t qf[8][4];
#pragma unroll
    for (int ks = 0; ks < 8; ks++) {
        int base = (16 * w + qrow) * AT_STRIDE + ks * 8 + qcol;
        qf[ks][0] = *(const uint32_t*)&Qs[base];
        qf[ks][1] = *(const uint32_t*)&Qs[base + 8 * AT_STRIDE];
        qf[ks][2] = *(const uint32_t*)&Qs[base + 4];
        qf[ks][3] = *(const uint32_t*)&Qs[base + 8 * AT_STRIDE + 4];
    }

    float oacc[8][4];
#pragma unroll
    for (int dn = 0; dn < 8; dn++)
#pragma unroll
        for (int e = 0; e < 4; e++) oacc[dn][e] = 0.f;
    float m0 = -1e30f, m1 = -1e30f, l0 = 0.f, l1 = 0.f;

    int njt = q0 / 64 + 1;
    for (int jt = 0; jt < njt; jt++) {
        if (jt + 1 < njt) issue_kv((jt + 1) * 64, (jt + 1) & 1);
        if (jt + 1 < njt) asm volatile("cp.async.wait_group 1;\n");
        else              asm volatile("cp.async.wait_group 0;\n");
        __syncthreads();

        const float* Ks = KV + (jt & 1) * 2 * AT_TILE;
        const float* Vs = Ks + AT_TILE;

        // S = Q @ K^T
        float sacc[8][4];
#pragma unroll
        for (int nt = 0; nt < 8; nt++)
#pragma unroll
            for (int e = 0; e < 4; e++) sacc[nt][e] = 0.f;
#pragma unroll
        for (int ks = 0; ks < 8; ks++) {
#pragma unroll
            for (int nt = 0; nt < 8; nt++) {
                uint32_t b0 = *(const uint32_t*)&Ks[(nt * 8 + qrow) * AT_STRIDE + ks * 8 + qcol];
                uint32_t b1 = *(const uint32_t*)&Ks[(nt * 8 + qrow) * AT_STRIDE + ks * 8 + qcol + 4];
                mma_tf32(sacc[nt][0], sacc[nt][1], sacc[nt][2], sacc[nt][3],
                         qf[ks][0], qf[ks][1], qf[ks][2], qf[ks][3], b0, b1);
            }
        }

        // causal mask on diagonal tile
        if (jt == njt - 1) {
            int row0 = q0 + 16 * w + qrow;
            int row1 = row0 + 8;
            int j0 = jt * 64;
#pragma unroll
            for (int nt = 0; nt < 8; nt++) {
                int col = j0 + nt * 8 + 2 * qcol;
                if (col     > row0) sacc[nt][0] = -1e30f;
                if (col + 1 > row0) sacc[nt][1] = -1e30f;
                if (col     > row1) sacc[nt][2] = -1e30f;
                if (col + 1 > row1) sacc[nt][3] = -1e30f;
            }
        }

        // row maxima (4-lane row groups: xor 1, 2)
        float mt0 = -1e30f, mt1 = -1e30f;
#pragma unroll
        for (int nt = 0; nt < 8; nt++) {
            mt0 = fmaxf(mt0, fmaxf(sacc[nt][0], sacc[nt][1]));
            mt1 = fmaxf(mt1, fmaxf(sacc[nt][2], sacc[nt][3]));
        }
        mt0 = fmaxf(mt0, __shfl_xor_sync(0xffffffffu, mt0, 1));
        mt0 = fmaxf(mt0, __shfl_xor_sync(0xffffffffu, mt0, 2));
        mt1 = fmaxf(mt1, __shfl_xor_sync(0xffffffffu, mt1, 1));
        mt1 = fmaxf(mt1, __shfl_xor_sync(0xffffffffu, mt1, 2));
        float mn0 = fmaxf(m0, mt0), mn1 = fmaxf(m1, mt1);
        float al0 = __expf(m0 - mn0), al1 = __expf(m1 - mn1);

        // P = exp(S - m), tf32-rounded (consistent numerator/denominator)
        float sum0 = 0.f, sum1 = 0.f;
#pragma unroll
        for (int nt = 0; nt < 8; nt++) {
            float p0 = rtf(__expf(sacc[nt][0] - mn0));
            float p1 = rtf(__expf(sacc[nt][1] - mn0));
            float p2 = rtf(__expf(sacc[nt][2] - mn1));
            float p3 = rtf(__expf(sacc[nt][3] - mn1));
            sacc[nt][0] = p0; sacc[nt][1] = p1; sacc[nt][2] = p2; sacc[nt][3] = p3;
            sum0 += p0 + p1; sum1 += p2 + p3;
        }
        sum0 += __shfl_xor_sync(0xffffffffu, sum0, 1);
        sum0 += __shfl_xor_sync(0xffffffffu, sum0, 2);
        sum1 += __shfl_xor_sync(0xffffffffu, sum1, 1);
        sum1 += __shfl_xor_sync(0xffffffffu, sum1, 2);
        l0 = l0 * al0 + sum0;
        l1 = l1 * al1 + sum1;
        m0 = mn0; m1 = mn1;

#pragma unroll
        for (int dn = 0; dn < 8; dn++) {
            oacc[dn][0] *= al0; oacc[dn][1] *= al0;
            oacc[dn][2] *= al1; oacc[dn][3] *= al1;
        }

        // O += P @ V  (P regs -> A-fragments via quad shuffles)
        int src1 = (lane & ~3) | (qcol >> 1);
        int src2 = src1 + 2;
        bool odd = (qcol & 1);
#pragma unroll
        for (int ks = 0; ks < 8; ks++) {
            float v00 = __shfl_sync(0xffffffffu, sacc[ks][0], src1);
            float v01 = __shfl_sync(0xffffffffu, sacc[ks][1], src1);
            float v10 = __shfl_sync(0xffffffffu, sacc[ks][2], src1);
            float v11 = __shfl_sync(0xffffffffu, sacc[ks][3], src1);
            float v20 = __shfl_sync(0xffffffffu, sacc[ks][0], src2);
            float v21 = __shfl_sync(0xffffffffu, sacc[ks][1], src2);
            float v30 = __shfl_sync(0xffffffffu, sacc[ks][2], src2);
            float v31 = __shfl_sync(0xffffffffu, sacc[ks][3], src2);
            uint32_t pa0 = __float_as_uint(odd ? v01 : v00);
            uint32_t pa1 = __float_as_uint(odd ? v11 : v10);
            uint32_t pa2 = __float_as_uint(odd ? v21 : v20);
            uint32_t pa3 = __float_as_uint(odd ? v31 : v30);
#pragma unroll
            for (int dn = 0; dn < 8; dn++) {
                uint32_t b0 = *(const uint32_t*)&Vs[(ks * 8 + qcol) * AT_STRIDE + dn * 8 + qrow];
                uint32_t b1 = *(const uint32_t*)&Vs[(ks * 8 + qcol + 4) * AT_STRIDE + dn * 8 + qrow];
                mma_tf32(oacc[dn][0], oacc[dn][1], oacc[dn][2], oacc[dn][3],
                         pa0, pa1, pa2, pa3, b0, b1);
            }
        }
        __syncthreads();   // protect stage before re-issue
    }

    // epilogue: normalize, tf32-round (feeds final GEMM), store
    float inv0 = 1.0f / l0, inv1 = 1.0f / l1;
    int row0 = q0 + 16 * w + qrow;
    float* op0 = outa + (size_t)(b * S_ + row0) * NQ_ + h * HD_;
    float* op1 = op0 + (size_t)8 * NQ_;
#pragma unroll
    for (int dn = 0; dn < 8; dn++) {
        int d = dn * 8 + 2 * qcol;
        *(float2*)(op0 + d) = make_float2(rtf(oacc[dn][0] * inv0), rtf(oacc[dn][1] * inv0));
        *(float2*)(op1 + d) = make_float2(rtf(oacc[dn][2] * inv1), rtf(oacc[dn][3] * inv1));
    }
}

// ---------------- launch --------------------------------------------------
extern "C" void kernel_launch(void* const* d_in, const int* in_sizes, int n_in,
                              void* d_out, int out_size)
{
    const float* x       = (const float*)d_in[0];
    const float* wq      = (const float*)d_in[1];
    const float* wk      = (const float*)d_in[2];
    const float* wv      = (const float*)d_in[3];
    const float* wo      = (const float*)d_in[4];
    const float* q_scale = (const float*)d_in[5];
    const float* k_scale = (const float*)d_in[6];
    const float* cosb    = (const float*)d_in[7];
    const float* sinb    = (const float*)d_in[8];
    float* out = (float*)d_out;

    float *q, *k, *v, *qn, *kn, *attn, *xr, *wqr, *wkr, *wvr, *wor;
    cudaGetSymbolAddress((void**)&q,    g_q);
    cudaGetSymbolAddress((void**)&k,    g_k);
    cudaGetSymbolAddress((void**)&v,    g_v);
    cudaGetSymbolAddress((void**)&qn,   g_qn);
    cudaGetSymbolAddress((void**)&kn,   g_kn);
    cudaGetSymbolAddress((void**)&attn, g_attn);
    cudaGetSymbolAddress((void**)&xr,   g_xr);
    cudaGetSymbolAddress((void**)&wqr,  g_wqr);
    cudaGetSymbolAddress((void**)&wkr,  g_wkr);
    cudaGetSymbolAddress((void**)&wvr,  g_wvr);
    cudaGetSymbolAddress((void**)&wor,  g_wor);

    cudaFuncSetAttribute(tf32_gemm_kernel,
                         cudaFuncAttributeMaxDynamicSharedMemorySize, GEMM_SMEM);
    cudaFuncSetAttribute(flash_attn_tc_kernel,
                         cudaFuncAttributeMaxDynamicSharedMemorySize, ATTN_SMEM_TC);

    // pre-round operands to tf32-representable fp32 (GEMM inner loop has no CVT)
    round_tf32_kernel<<<2048, 256>>>((const float4*)x,  (float4*)xr,  (M_ * D_) / 4);
    round_tf32_kernel<<<1024, 256>>>((const float4*)wq, (float4*)wqr, (D_ * NQ_) / 4);
    round_tf32_kernel<<<512, 256>>>((const float4*)wk, (float4*)wkr, (D_ * NKVD_) / 4);
    round_tf32_kernel<<<512, 256>>>((const float4*)wv, (float4*)wvr, (D_ * NKVD_) / 4);
    round_tf32_kernel<<<1024, 256>>>((const float4*)wo, (float4*)wor, (NQ_ * D_) / 4);

    // QKV projections
    tf32_gemm_kernel<<<dim3(NQ_ / GBN, M_ / GBM), 256, GEMM_SMEM>>>(xr, wqr, q, M_, NQ_, D_);
    tf32_gemm_kernel<<<dim3(NKVD_ / GBN, M_ / GBM), 256, GEMM_SMEM>>>(xr, wkr, k, M_, NKVD_, D_);
    tf32_gemm_kernel<<<dim3(NKVD_ / GBN, M_ / GBM), 256, GEMM_SMEM>>>(xr, wvr, v, M_, NKVD_, D_);

    // RMSNorm + RoPE (q pre-scaled by 1/sqrt(64), both tf32-rounded)
    norm_rope_kernel<<<(M_ * NH_) / 8, 256>>>(q, qn, q_scale, cosb, sinb, NH_, 0.125f);
    norm_rope_kernel<<<(M_ * NKV_) / 8, 256>>>(k, kn, k_scale, cosb, sinb, NKV_, 1.0f);

    // tensor-core flash attention
    flash_attn_tc_kernel<<<dim3(S_ / 64, B_ * NH_), 128, ATTN_SMEM_TC>>>(qn, kn, v, attn);

    // output projection
    tf32_gemm_kernel<<<dim3(D_ / GBN, M_ / GBM), 256, GEMM_SMEM>>>(attn, wor, out, M_, D_, NQ_);
}

// round 13
// speedup vs baseline: 5.0632x; 1.0315x over previous
#include <cuda_runtime.h>
#include <cstddef>
#include <cstdint>

// Problem dims (fixed per reference)
#define B_    2
#define S_    2048
#define D_    2048
#define NH_   32
#define NKV_  8
#define HD_   64
#define M_    (B_ * S_)          // 4096
#define NQ_   (NH_ * HD_)        // 2048
#define NKVD_ (NKV_ * HD_)       // 512
#define KVW_  1024               // fused k|v width

// ---------------- scratch (no allocations allowed) ----------------
__device__ float g_q[(size_t)M_ * NQ_];
__device__ float g_kv[(size_t)M_ * KVW_];   // fused raw k (cols 0-511) | v (512-1023)
__device__ float g_qn[(size_t)M_ * NQ_];    // (B, NH, S, HD)  tf32-rounded, pre-scaled 1/8
__device__ float g_kn[(size_t)M_ * NKVD_];  // (B, NKV, S, HD) tf32-rounded
__device__ float g_attn[(size_t)M_ * NQ_];  // (M, NH*HD)      tf32-rounded at epilogue
__device__ float g_xr[(size_t)M_ * D_];     // tf32-rounded x
__device__ float g_wqr[(size_t)D_ * NQ_];
__device__ float g_wkv[(size_t)D_ * KVW_];  // rounded wk | wv packed
__device__ float g_wor[(size_t)NQ_ * D_];

__device__ __forceinline__ uint32_t f2tf32(float f) {
    uint32_t r;
    asm("cvt.rna.tf32.f32 %0, %1;" : "=r"(r) : "f"(f));
    return r;
}
__device__ __forceinline__ float rtf(float f) { return __uint_as_float(f2tf32(f)); }

__device__ __forceinline__ void mma_tf32(
    float& c0, float& c1, float& c2, float& c3,
    uint32_t a0, uint32_t a1, uint32_t a2, uint32_t a3,
    uint32_t b0, uint32_t b1)
{
    asm volatile(
        "mma.sync.aligned.m16n8k8.row.col.f32.tf32.tf32.f32 "
        "{%0,%1,%2,%3}, {%4,%5,%6,%7}, {%8,%9}, {%0,%1,%2,%3};\n"
        : "+f"(c0), "+f"(c1), "+f"(c2), "+f"(c3)
        : "r"(a0), "r"(a1), "r"(a2), "r"(a3), "r"(b0), "r"(b1));
}

// ---------------- elementwise tf32 pre-round -------------------------------
__global__ void round_tf32_kernel(const float4* __restrict__ in,
                                  float4* __restrict__ out, int n4)
{
    for (int i = blockIdx.x * blockDim.x + threadIdx.x; i < n4;
         i += gridDim.x * blockDim.x) {
        float4 v = in[i];
        v.x = rtf(v.x); v.y = rtf(v.y); v.z = rtf(v.z); v.w = rtf(v.w);
        out[i] = v;
    }
}

// round + pack into strided destination (for wk|wv fusion)
__global__ void round_tf32_pack_kernel(const float4* __restrict__ in,
                                       float4* __restrict__ out, int n4,
                                       int row4, int ostride4, int ooff4)
{
    for (int i = blockIdx.x * blockDim.x + threadIdx.x; i < n4;
         i += gridDim.x * blockDim.x) {
        float4 v = in[i];
        v.x = rtf(v.x); v.y = rtf(v.y); v.z = rtf(v.z); v.w = rtf(v.w);
        int row = i / row4, col = i - row * row4;
        out[(size_t)row * ostride4 + ooff4 + col] = v;
    }
}

// ---------------- TF32 GEMM: 3-stage cp.async + ldmatrix A -----------------
#define GBM 128
#define GBN 128
#define GBK 32
#define AS_STRIDE 36
#define BS_STRIDE 136
#define A_SZ (GBM * AS_STRIDE)
#define B_SZ (GBK * BS_STRIDE)
#define STAGE_SZ (A_SZ + B_SZ)      // 8960 floats
#define GEMM_SMEM (3 * STAGE_SZ * 4) // 107520 bytes

__device__ __forceinline__ void gemm_issue_tile(
    const float* __restrict__ A, const float* __restrict__ B,
    int N, int K, int m0, int n0, int k0,
    float* As, float* Bs, int t)
{
#pragma unroll
    for (int u = 0; u < 4; u++) {
        int lin = u * 1024 + t * 4;
        int r = lin >> 5, c = lin & 31;
        const float* gp = A + (size_t)(m0 + r) * K + k0 + c;
        uint32_t sp = (uint32_t)__cvta_generic_to_shared(As + r * AS_STRIDE + c);
        asm volatile("cp.async.cg.shared.global [%0], [%1], 16;\n" :: "r"(sp), "l"(gp));
    }
#pragma unroll
    for (int u = 0; u < 4; u++) {
        int lin = u * 1024 + t * 4;
        int r = lin >> 7, c = lin & 127;
        const float* gp = B + (size_t)(k0 + r) * N + n0 + c;
        uint32_t sp = (uint32_t)__cvta_generic_to_shared(Bs + r * BS_STRIDE + c);
        asm volatile("cp.async.cg.shared.global [%0], [%1], 16;\n" :: "r"(sp), "l"(gp));
    }
    asm volatile("cp.async.commit_group;\n");
}

__global__ __launch_bounds__(256) void tf32_gemm_kernel(
    const float* __restrict__ A, const float* __restrict__ B,
    float* __restrict__ C, int M, int N, int K)
{
    extern __shared__ float gsm[];
    uint32_t gsm_u32 = (uint32_t)__cvta_generic_to_shared(gsm);

    int t    = threadIdx.x;
    int wid  = t >> 5;
    int lane = t & 31;
    int warp_m = wid >> 2;
    int warp_n = wid & 3;
    int m0 = blockIdx.y * GBM;
    int n0 = blockIdx.x * GBN;
    int qrow = lane >> 2;
    int qcol = lane & 3;

    // ldmatrix lane base: tile = lane>>3 selects (row+8?, k+4?) quadrant
    int ltile = lane >> 3, lr = lane & 7;
    int lrow  = warp_m * 64 + ((ltile & 1) << 3) + lr;
    int lkb   = (ltile >> 1) << 2;                 // +4 floats for k-hi tiles
    int lmbase = lrow * AS_STRIDE + lkb;           // float index within As

    float acc[4][4][4];
#pragma unroll
    for (int mt = 0; mt < 4; mt++)
#pragma unroll
        for (int nt = 0; nt < 4; nt++)
#pragma unroll
            for (int e = 0; e < 4; e++) acc[mt][nt][e] = 0.f;

    int ntiles = K / GBK;
    gemm_issue_tile(A, B, N, K, m0, n0, 0, gsm, gsm + A_SZ, t);
    gemm_issue_tile(A, B, N, K, m0, n0, GBK,
                    gsm + STAGE_SZ, gsm + STAGE_SZ + A_SZ, t);

    for (int it = 0; it < ntiles; it++) {
        int cur = it % 3;
        if (it + 2 < ntiles) {
            int s = (it + 2) % 3;
            gemm_issue_tile(A, B, N, K, m0, n0, (it + 2) * GBK,
                            gsm + s * STAGE_SZ, gsm + s * STAGE_SZ + A_SZ, t);
            asm volatile("cp.async.wait_group 2;\n");
        } else if (it + 1 < ntiles) {
            asm volatile("cp.async.wait_group 1;\n");
        } else {
            asm volatile("cp.async.wait_group 0;\n");
        }
        __syncthreads();

        uint32_t As_u32 = gsm_u32 + (uint32_t)(cur * STAGE_SZ) * 4;
        const uint32_t* Bs = (const uint32_t*)(gsm + cur * STAGE_SZ + A_SZ);

#pragma unroll
        for (int kk = 0; kk < 4; kk++) {
            uint32_t bf[4][2];
            int brow = kk * 8 + qcol;
            int bcol = warp_n * 32 + qrow;
#pragma unroll
            for (int nt = 0; nt < 4; nt++) {
                bf[nt][0] = Bs[brow * BS_STRIDE + bcol + nt * 8];
                bf[nt][1] = Bs[(brow + 4) * BS_STRIDE + bcol + nt * 8];
            }
#pragma unroll
            for (int mt = 0; mt < 4; mt++) {
                uint32_t addr = As_u32 +
                    (uint32_t)(lmbase + mt * (16 * AS_STRIDE) + kk * 8) * 4;
                uint32_t a0, a1, a2, a3;
                asm volatile(
                    "ldmatrix.sync.aligned.m8n8.x4.shared.b16 {%0,%1,%2,%3}, [%4];\n"
                    : "=r"(a0), "=r"(a1), "=r"(a2), "=r"(a3) : "r"(addr));
#pragma unroll
                for (int nt = 0; nt < 4; nt++)
                    mma_tf32(acc[mt][nt][0], acc[mt][nt][1],
                             acc[mt][nt][2], acc[mt][nt][3],
                             a0, a1, a2, a3, bf[nt][0], bf[nt][1]);
            }
        }
        __syncthreads();
    }

#pragma unroll
    for (int mt = 0; mt < 4; mt++) {
#pragma unroll
        for (int nt = 0; nt < 4; nt++) {
            int row = m0 + warp_m * 64 + mt * 16 + qrow;
            int col = n0 + warp_n * 32 + nt * 8 + 2 * qcol;
            *(float2*)(C + (size_t)row * N + col) =
                make_float2(acc[mt][nt][0], acc[mt][nt][1]);
            *(float2*)(C + (size_t)(row + 8) * N + col) =
                make_float2(acc[mt][nt][2], acc[mt][nt][3]);
        }
    }
}

// ---------------- RMSNorm + RoPE, tf32-rounded output ----------------------
__global__ __launch_bounds__(256) void norm_rope_kernel(
    const float* __restrict__ in, float* __restrict__ out,
    const float* __restrict__ scale,
    const float* __restrict__ cosb, const float* __restrict__ sinb,
    int nheads, int in_stride, float smul)
{
    int warp = (blockIdx.x * blockDim.x + threadIdx.x) >> 5;
    int lane = threadIdx.x & 31;
    int row  = warp / nheads;
    int h    = warp - row * nheads;
    int s    = row & (S_ - 1);
    int b    = row >> 11;

    const float* p = in + (size_t)row * in_stride + h * HD_;
    float x0 = p[lane];
    float x1 = p[lane + 32];
    float ss = x0 * x0 + x1 * x1;
#pragma unroll
    for (int o = 16; o; o >>= 1) ss += __shfl_xor_sync(0xffffffffu, ss, o);
    float rr = rsqrtf(ss * (1.0f / HD_) + 1e-6f);
    float n0 = x0 * rr * scale[lane];
    float n1 = x1 * rr * scale[lane + 32];

    float c0 = cosb[s * HD_ + lane];
    float c1 = cosb[s * HD_ + lane + 32];
    float s0 = sinb[s * HD_ + lane];
    float s1 = sinb[s * HD_ + lane + 32];
    float o0 = (n0 * c0 - n1 * s0) * smul;
    float o1 = (n1 * c1 + n0 * s1) * smul;

    float* q = out + ((size_t)(b * nheads + h) * S_ + s) * HD_;
    q[lane]      = rtf(o0);
    q[lane + 32] = rtf(o1);
}

// ---------------- tensor-core flash attention (causal, GQA) ----------------
// 128 threads (4 warps). CTA: 64 q-rows; warp w: rows 16w..16w+15.
// QK and PV via mma.m16n8k8.tf32. K/V tiles double-buffered cp.async.
// V comes from the fused kv buffer: row stride KVW_, col offset 512 + hk*64.
#define AT_STRIDE 68
#define AT_TILE (64 * AT_STRIDE)
#define ATTN_SMEM_TC (5 * AT_TILE * 4)   // Q + 2*(K,V) = 87040 B

__global__ __launch_bounds__(128) void flash_attn_tc_kernel(
    const float* __restrict__ qn, const float* __restrict__ kn,
    const float* __restrict__ kv, float* __restrict__ outa)
{
    extern __shared__ float sm[];
    float* Qs = sm;
    float* KV = sm + AT_TILE;    // [stage][K tile | V tile]

    int t = threadIdx.x;
    int lane = t & 31;
    int w = t >> 5;
    int qrow = lane >> 2;
    int qcol = lane & 3;
    int bh = blockIdx.y;
    int b  = bh >> 5;
    int h  = bh & 31;
    int hk = h >> 2;
    int q0 = blockIdx.x * 64;

    const float* kb = kn + ((size_t)(b * NKV_ + hk) * S_) * HD_;
    const float* vb = kv + (size_t)(b * S_) * KVW_ + 512 + hk * HD_;

    // load Q tile (values pre-scaled by 1/8 and tf32-rounded upstream)
    const float* qb = qn + ((size_t)bh * S_ + q0) * HD_;
#pragma unroll
    for (int u = 0; u < 8; u++) {
        int idx4 = u * 128 + t;
        int row = idx4 >> 4, ch = idx4 & 15;
        *(float4*)&Qs[row * AT_STRIDE + ch * 4] =
            *(const float4*)(qb + (size_t)row * HD_ + ch * 4);
    }

    // issue K/V tile j0 into stage s
    auto issue_kv = [&](int j0, int s) {
        float* Kd = KV + s * 2 * AT_TILE;
        float* Vd = Kd + AT_TILE;
#pragma unroll
        for (int u = 0; u < 8; u++) {
            int idx4 = u * 128 + t;
            int row = idx4 >> 4, ch = idx4 & 15;
            const float* gk = kb + (size_t)(j0 + row) * HD_ + ch * 4;
            uint32_t sk = (uint32_t)__cvta_generic_to_shared(Kd + row * AT_STRIDE + ch * 4);
            asm volatile("cp.async.cg.shared.global [%0], [%1], 16;\n" :: "r"(sk), "l"(gk));
            const float* gv = vb + (size_t)(j0 + row) * KVW_ + ch * 4;
            uint32_t sv = (uint32_t)__cvta_generic_to_shared(Vd + row * AT_STRIDE + ch * 4);
            asm volatile("cp.async.cg.shared.global [%0], [%1], 16;\n" :: "r"(sv), "l"(gv));
        }
        asm volatile("cp.async.commit_group;\n");
    };

    issue_kv(0, 0);
    __syncthreads();   // Qs ready for fragment builds

    // Q fragments: [ks][a0..a3]
    uint32_t qf[8][4];
#pragma unroll
    for (int ks = 0; ks < 8; ks++) {
        int base = (16 * w + qrow) * AT_STRIDE + ks * 8 + qcol;
        qf[ks][0] = *(const uint32_t*)&Qs[base];
        qf[ks][1] = *(const uint32_t*)&Qs[base + 8 * AT_STRIDE];
        qf[ks][2] = *(const uint32_t*)&Qs[base + 4];
        qf[ks][3] = *(const uint32_t*)&Qs[base + 8 * AT_STRIDE + 4];
    }

    float oacc[8][4];
#pragma unroll
    for (int dn = 0; dn < 8; dn++)
#pragma unroll
        for (int e = 0; e < 4; e++) oacc[dn][e] = 0.f;
    float m0 = -1e30f, m1 = -1e30f, l0 = 0.f, l1 = 0.f;

    int njt = q0 / 64 + 1;
    for (int jt = 0; jt < njt; jt++) {
        if (jt + 1 < njt) issue_kv((jt + 1) * 64, (jt + 1) & 1);
        if (jt + 1 < njt) asm volatile("cp.async.wait_group 1;\n");
        else              asm volatile("cp.async.wait_group 0;\n");
        __syncthreads();

        const float* Ks = KV + (jt & 1) * 2 * AT_TILE;
        const float* Vs = Ks + AT_TILE;

        // S = Q @ K^T
        float sacc[8][4];
#pragma unroll
        for (int nt = 0; nt < 8; nt++)
#pragma unroll
            for (int e = 0; e < 4; e++) sacc[nt][e] = 0.f;
#pragma unroll
        for (int ks = 0; ks < 8; ks++) {
#pragma unroll
            for (int nt = 0; nt < 8; nt++) {
                uint32_t b0 = *(const uint32_t*)&Ks[(nt * 8 + qrow) * AT_STRIDE + ks * 8 + qcol];
                uint32_t b1 = *(const uint32_t*)&Ks[(nt * 8 + qrow) * AT_STRIDE + ks * 8 + qcol + 4];
                mma_tf32(sacc[nt][0], sacc[nt][1], sacc[nt][2], sacc[nt][3],
                         qf[ks][0], qf[ks][1], qf[ks][2], qf[ks][3], b0, b1);
            }
        }

        // causal mask on diagonal tile
        if (jt == njt - 1) {
            int row0 = q0 + 16 * w + qrow;
            int row1 = row0 + 8;
            int j0 = jt * 64;
#pragma unroll
            for (int nt = 0; nt < 8; nt++) {
                int col = j0 + nt * 8 + 2 * qcol;
                if (col     > row0) sacc[nt][0] = -1e30f;
                if (col + 1 > row0) sacc[nt][1] = -1e30f;
                if (col     > row1) sacc[nt][2] = -1e30f;
                if (col + 1 > row1) sacc[nt][3] = -1e30f;
            }
        }

        // row maxima (4-lane row groups: xor 1, 2)
        float mt0 = -1e30f, mt1 = -1e30f;
#pragma unroll
        for (int nt = 0; nt < 8; nt++) {
            mt0 = fmaxf(mt0, fmaxf(sacc[nt][0], sacc[nt][1]));
            mt1 = fmaxf(mt1, fmaxf(sacc[nt][2], sacc[nt][3]));
        }
        mt0 = fmaxf(mt0, __shfl_xor_sync(0xffffffffu, mt0, 1));
        mt0 = fmaxf(mt0, __shfl_xor_sync(0xffffffffu, mt0, 2));
        mt1 = fmaxf(mt1, __shfl_xor_sync(0xffffffffu, mt1, 1));
        mt1 = fmaxf(mt1, __shfl_xor_sync(0xffffffffu, mt1, 2));
        float mn0 = fmaxf(m0, mt0), mn1 = fmaxf(m1, mt1);
        float al0 = __expf(m0 - mn0), al1 = __expf(m1 - mn1);

        // P = exp(S - m), tf32-rounded (consistent numerator/denominator)
        float sum0 = 0.f, sum1 = 0.f;
#pragma unroll
        for (int nt = 0; nt < 8; nt++) {
            float p0 = rtf(__expf(sacc[nt][0] - mn0));
            float p1 = rtf(__expf(sacc[nt][1] - mn0));
            float p2 = rtf(__expf(sacc[nt][2] - mn1));
            float p3 = rtf(__expf(sacc[nt][3] - mn1));
            sacc[nt][0] = p0; sacc[nt][1] = p1; sacc[nt][2] = p2; sacc[nt][3] = p3;
            sum0 += p0 + p1; sum1 += p2 + p3;
        }
        sum0 += __shfl_xor_sync(0xffffffffu, sum0, 1);
        sum0 += __shfl_xor_sync(0xffffffffu, sum0, 2);
        sum1 += __shfl_xor_sync(0xffffffffu, sum1, 1);
        sum1 += __shfl_xor_sync(0xffffffffu, sum1, 2);
        l0 = l0 * al0 + sum0;
        l1 = l1 * al1 + sum1;
        m0 = mn0; m1 = mn1;

#pragma unroll
        for (int dn = 0; dn < 8; dn++) {
            oacc[dn][0] *= al0; oacc[dn][1] *= al0;
            oacc[dn][2] *= al1; oacc[dn][3] *= al1;
        }

        // O += P @ V  (P regs -> A-fragments via quad shuffles)
        int src1 = (lane & ~3) | (qcol >> 1);
        int src2 = src1 + 2;
        bool odd = (qcol & 1);
#pragma unroll
        for (int ks = 0; ks < 8; ks++) {
            float v00 = __shfl_sync(0xffffffffu, sacc[ks][0], src1);
            float v01 = __shfl_sync(0xffffffffu, sacc[ks][1], src1);
            float v10 = __shfl_sync(0xffffffffu, sacc[ks][2], src1);
            float v11 = __shfl_sync(0xffffffffu, sacc[ks][3], src1);
            float v20 = __shfl_sync(0xffffffffu, sacc[ks][0], src2);
            float v21 = __shfl_sync(0xffffffffu, sacc[ks][1], src2);
            float v30 = __shfl_sync(0xffffffffu, sacc[ks][2], src2);
            float v31 = __shfl_sync(0xffffffffu, sacc[ks][3], src2);
            uint32_t pa0 = __float_as_uint(odd ? v01 : v00);
            uint32_t pa1 = __float_as_uint(odd ? v11 : v10);
            uint32_t pa2 = __float_as_uint(odd ? v21 : v20);
            uint32_t pa3 = __float_as_uint(odd ? v31 : v30);
#pragma unroll
            for (int dn = 0; dn < 8; dn++) {
                uint32_t b0 = *(const uint32_t*)&Vs[(ks * 8 + qcol) * AT_STRIDE + dn * 8 + qrow];
                uint32_t b1 = *(const uint32_t*)&Vs[(ks * 8 + qcol + 4) * AT_STRIDE + dn * 8 + qrow];
                mma_tf32(oacc[dn][0], oacc[dn][1], oacc[dn][2], oacc[dn][3],
                         pa0, pa1, pa2, pa3, b0, b1);
            }
        }
        __syncthreads();   // protect stage before re-issue
    }

    // epilogue: normalize, tf32-round (feeds final GEMM), store
    float inv0 = 1.0f / l0, inv1 = 1.0f / l1;
    int row0 = q0 + 16 * w + qrow;
    float* op0 = outa + (size_t)(b * S_ + row0) * NQ_ + h * HD_;
    float* op1 = op0 + (size_t)8 * NQ_;
#pragma unroll
    for (int dn = 0; dn < 8; dn++) {
        int d = dn * 8 + 2 * qcol;
        *(float2*)(op0 + d) = make_float2(rtf(oacc[dn][0] * inv0), rtf(oacc[dn][1] * inv0));
        *(float2*)(op1 + d) = make_float2(rtf(oacc[dn][2] * inv1), rtf(oacc[dn][3] * inv1));
    }
}

// ---------------- launch --------------------------------------------------
extern "C" void kernel_launch(void* const* d_in, const int* in_sizes, int n_in,
                              void* d_out, int out_size)
{
    const float* x       = (const float*)d_in[0];
    const float* wq      = (const float*)d_in[1];
    const float* wk      = (const float*)d_in[2];
    const float* wv      = (const float*)d_in[3];
    const float* wo      = (const float*)d_in[4];
    const float* q_scale = (const float*)d_in[5];
    const float* k_scale = (const float*)d_in[6];
    const float* cosb    = (const float*)d_in[7];
    const float* sinb    = (const float*)d_in[8];
    float* out = (float*)d_out;

    float *q, *kv, *qn, *kn, *attn, *xr, *wqr, *wkv, *wor;
    cudaGetSymbolAddress((void**)&q,    g_q);
    cudaGetSymbolAddress((void**)&kv,   g_kv);
    cudaGetSymbolAddress((void**)&qn,   g_qn);
    cudaGetSymbolAddress((void**)&kn,   g_kn);
    cudaGetSymbolAddress((void**)&attn, g_attn);
    cudaGetSymbolAddress((void**)&xr,   g_xr);
    cudaGetSymbolAddress((void**)&wqr,  g_wqr);
    cudaGetSymbolAddress((void**)&wkv,  g_wkv);
    cudaGetSymbolAddress((void**)&wor,  g_wor);

    cudaFuncSetAttribute(tf32_gemm_kernel,
                         cudaFuncAttributeMaxDynamicSharedMemorySize, GEMM_SMEM);
    cudaFuncSetAttribute(flash_attn_tc_kernel,
                         cudaFuncAttributeMaxDynamicSharedMemorySize, ATTN_SMEM_TC);

    // pre-round operands to tf32-representable fp32
    round_tf32_kernel<<<2048, 256>>>((const float4*)x,  (float4*)xr,  (M_ * D_) / 4);
    round_tf32_kernel<<<1024, 256>>>((const float4*)wq, (float4*)wqr, (D_ * NQ_) / 4);
    round_tf32_pack_kernel<<<512, 256>>>((const float4*)wk, (float4*)wkv,
                                         (D_ * NKVD_) / 4, NKVD_ / 4, KVW_ / 4, 0);
    round_tf32_pack_kernel<<<512, 256>>>((const float4*)wv, (float4*)wkv,
                                         (D_ * NKVD_) / 4, NKVD_ / 4, KVW_ / 4, NKVD_ / 4);
    round_tf32_kernel<<<1024, 256>>>((const float4*)wo, (float4*)wor, (NQ_ * D_) / 4);

    // projections: q, and fused k|v
    tf32_gemm_kernel<<<dim3(NQ_ / GBN, M_ / GBM), 256, GEMM_SMEM>>>(xr, wqr, q, M_, NQ_, D_);
    tf32_gemm_kernel<<<dim3(KVW_ / GBN, M_ / GBM), 256, GEMM_SMEM>>>(xr, wkv, kv, M_, KVW_, D_);

    // RMSNorm + RoPE (q pre-scaled by 1/sqrt(64); k read from fused kv, stride 1024)
    norm_rope_kernel<<<(M_ * NH_) / 8, 256>>>(q, qn, q_scale, cosb, sinb, NH_, NQ_, 0.125f);
    norm_rope_kernel<<<(M_ * NKV_) / 8, 256>>>(kv, kn, k_scale, cosb, sinb, NKV_, KVW_, 1.0f);

    // tensor-core flash attention (v read from fused kv)
    flash_attn_tc_kernel<<<dim3(S_ / 64, B_ * NH_), 128, ATTN_SMEM_TC>>>(qn, kn, kv, attn);

    // output projection
    tf32_gemm_kernel<<<dim3(D_ / GBN, M_ / GBM), 256, GEMM_SMEM>>>(attn, wor, out, M_, D_, NQ_);
}